// round 4
// baseline (speedup 1.0000x reference)
#include <cuda_runtime.h>
#include <math.h>

#define T_TOK 1024
#define HDIM  2048
#define NEXP  16
#define IDIM  768
#define CAP   1024   // worst-case tokens per expert

// -------- device scratch (no allocs allowed) --------
__device__ int   d_cnt[NEXP];
__device__ int   d_tok[NEXP * CAP];
__device__ float d_wt [NEXP * CAP];
__device__ float d_act[(size_t)NEXP * CAP * IDIM];   // ~50 MB

// -------- packed f32x2 helpers (sm_103a) --------
#define FFMA2(acc, a, b) \
    asm("fma.rn.f32x2 %0, %1, %2, %0;" : "+l"(acc) : "l"(a), "l"(b))

#define PACK2(out, f) do { \
    unsigned int _u = __float_as_uint(f); \
    asm("mov.b64 %0, {%1, %1};" : "=l"(out) : "r"(_u)); \
} while (0)

#define UNPACK2(lo, hi, in) do { \
    unsigned int _l, _h; \
    asm("mov.b64 {%0, %1}, %2;" : "=r"(_l), "=r"(_h) : "l"(in)); \
    lo = __uint_as_float(_l); hi = __uint_as_float(_h); \
} while (0)

// ============================================================
// Kernel 0: zero output accumulator region + expert counters
// ============================================================
__global__ void zero_kernel(float* __restrict__ out) {
    int i = blockIdx.x * blockDim.x + threadIdx.x;    // 524288 float4 = T*H floats
    float4 z = make_float4(0.f, 0.f, 0.f, 0.f);
    reinterpret_cast<float4*>(out)[i] = z;
    if (blockIdx.x == 0 && threadIdx.x < NEXP) d_cnt[threadIdx.x] = 0;
}

// ============================================================
// Kernel 1: router — logits, top-2, normalized weights, token lists
// one warp per token
// ============================================================
__global__ __launch_bounds__(256) void router_kernel(
    const float* __restrict__ x,        // [T, H]
    const float* __restrict__ gw,       // [E, H]
    float* __restrict__ logits_out)     // [T, E]
{
    int warp = threadIdx.x >> 5;
    int lane = threadIdx.x & 31;
    int t = blockIdx.x * 8 + warp;
    __shared__ float lg[8][NEXP];

    const float* xr = x + (size_t)t * HDIM;
    #pragma unroll 1
    for (int e = 0; e < NEXP; e++) {
        const float* g = gw + (size_t)e * HDIM;
        float s = 0.f;
        for (int k = lane; k < HDIM; k += 32) s += xr[k] * g[k];
        #pragma unroll
        for (int o = 16; o; o >>= 1) s += __shfl_xor_sync(0xffffffffu, s, o);
        if (lane == 0) lg[warp][e] = s;
    }
    __syncwarp();

    if (lane < NEXP) logits_out[t * NEXP + lane] = lg[warp][lane];

    if (lane == 0) {
        int i0 = 0; float v0 = lg[warp][0];
        #pragma unroll
        for (int e = 1; e < NEXP; e++) { float v = lg[warp][e]; if (v > v0) { v0 = v; i0 = e; } }
        int i1 = -1; float v1 = -3.4e38f;
        #pragma unroll
        for (int e = 0; e < NEXP; e++) { if (e == i0) continue; float v = lg[warp][e]; if (v > v1) { v1 = v; i1 = e; } }
        // normalized top-2 weights (softmax normalizer cancels)
        float w0 = 1.f / (1.f + expf(v1 - v0));
        float w1 = 1.f - w0;
        int p0 = atomicAdd(&d_cnt[i0], 1);
        d_tok[i0 * CAP + p0] = t;  d_wt[i0 * CAP + p0] = w0;
        int p1 = atomicAdd(&d_cnt[i1], 1);
        d_tok[i1 * CAP + p1] = t;  d_wt[i1 * CAP + p1] = w1;
    }
}

// ============================================================
// Kernel 2: grouped GEMM1 + fused SiLU·up
//   per expert e: H[cnt,1536] = X_e @ w1_e^T ; act = silu(g)*u -> d_act
//   tile: BM=128 tokens x BN=64 act-cols (gate AND up columns together)
// ============================================================
#define BM 128
#define BN 64
#define KT 16

__global__ __launch_bounds__(256) void gemm1_kernel(
    const float* __restrict__ x,     // [T, H]
    const float* __restrict__ w1)    // [E, 2I, H]
{
    const int e   = blockIdx.z;
    const int cnt = d_cnt[e];
    const int m0  = blockIdx.y * BM;
    if (m0 >= cnt) return;
    const int n0  = blockIdx.x * BN;

    __shared__ float As[KT][BM];
    __shared__ float Bg[KT][BN];
    __shared__ float Bu[KT][BN];

    const int tid = threadIdx.x;
    const int tx  = tid & 15;     // n: tx*4 .. +3
    const int ty  = tid >> 4;     // m: ty*8 .. +7

    int tokRow[2];
    #pragma unroll
    for (int i = 0; i < 2; i++) {
        int idx = tid + i * 256;
        int row = idx >> 2;
        int gr  = m0 + row;
        tokRow[i] = (gr < cnt) ? d_tok[e * CAP + gr] : 0;
    }

    const float* w1g = w1 + (size_t)e * (2 * IDIM) * HDIM + (size_t)n0 * HDIM;
    const float* w1u = w1g + (size_t)IDIM * HDIM;

    unsigned long long accG[4][4], accU[4][4];
    #pragma unroll
    for (int i = 0; i < 4; i++)
        #pragma unroll
        for (int j = 0; j < 4; j++) { accG[i][j] = 0ull; accU[i][j] = 0ull; }

    for (int k0 = 0; k0 < HDIM; k0 += KT) {
        // ---- load A tile (gathered token rows), store transposed ----
        #pragma unroll
        for (int i = 0; i < 2; i++) {
            int idx = tid + i * 256;
            int row = idx >> 2, q = idx & 3;
            float4 v = *reinterpret_cast<const float4*>(x + (size_t)tokRow[i] * HDIM + k0 + q * 4);
            As[q * 4 + 0][row] = v.x; As[q * 4 + 1][row] = v.y;
            As[q * 4 + 2][row] = v.z; As[q * 4 + 3][row] = v.w;
        }
        // ---- load B tiles (gate + up weight rows), store transposed ----
        {
            int row = tid >> 2, q = tid & 3;
            float4 vg = *reinterpret_cast<const float4*>(w1g + (size_t)row * HDIM + k0 + q * 4);
            Bg[q * 4 + 0][row] = vg.x; Bg[q * 4 + 1][row] = vg.y;
            Bg[q * 4 + 2][row] = vg.z; Bg[q * 4 + 3][row] = vg.w;
            float4 vu = *reinterpret_cast<const float4*>(w1u + (size_t)row * HDIM + k0 + q * 4);
            Bu[q * 4 + 0][row] = vu.x; Bu[q * 4 + 1][row] = vu.y;
            Bu[q * 4 + 2][row] = vu.z; Bu[q * 4 + 3][row] = vu.w;
        }
        __syncthreads();

        #pragma unroll
        for (int kk = 0; kk < KT; kk++) {
            ulonglong2 a01 = *reinterpret_cast<const ulonglong2*>(&As[kk][ty * 8]);
            ulonglong2 a23 = *reinterpret_cast<const ulonglong2*>(&As[kk][ty * 8 + 4]);
            unsigned long long ap[4] = { a01.x, a01.y, a23.x, a23.y };
            float4 bg4 = *reinterpret_cast<const float4*>(&Bg[kk][tx * 4]);
            float4 bu4 = *reinterpret_cast<const float4*>(&Bu[kk][tx * 4]);
            unsigned long long bg[4], bu[4];
            PACK2(bg[0], bg4.x); PACK2(bg[1], bg4.y); PACK2(bg[2], bg4.z); PACK2(bg[3], bg4.w);
            PACK2(bu[0], bu4.x); PACK2(bu[1], bu4.y); PACK2(bu[2], bu4.z); PACK2(bu[3], bu4.w);
            #pragma unroll
            for (int mp = 0; mp < 4; mp++)
                #pragma unroll
                for (int n = 0; n < 4; n++) {
                    FFMA2(accG[mp][n], ap[mp], bg[n]);
                    FFMA2(accU[mp][n], ap[mp], bu[n]);
                }
        }
        __syncthreads();
    }

    // ---- epilogue: act = silu(g) * u ----
    #pragma unroll
    for (int mp = 0; mp < 4; mp++) {
        int r0 = m0 + ty * 8 + 2 * mp;
        int r1 = r0 + 1;
        size_t b0 = ((size_t)e * CAP + r0) * IDIM + n0 + tx * 4;
        size_t b1 = ((size_t)e * CAP + r1) * IDIM + n0 + tx * 4;
        #pragma unroll
        for (int n = 0; n < 4; n++) {
            float gl, gh, ul, uh;
            UNPACK2(gl, gh, accG[mp][n]);
            UNPACK2(ul, uh, accU[mp][n]);
            if (r0 < cnt) d_act[b0 + n] = gl / (1.f + expf(-gl)) * ul;
            if (r1 < cnt) d_act[b1 + n] = gh / (1.f + expf(-gh)) * uh;
        }
    }
}

// ============================================================
// Kernel 3: grouped GEMM2 + weighted atomic scatter-add
//   per expert e: Y[cnt,2048] = act_e @ w2_e^T ; out[tok] += w * Y
// ============================================================
__global__ __launch_bounds__(256) void gemm2_kernel(
    const float* __restrict__ w2,    // [E, H, I]
    float* __restrict__ out)         // [T, H]
{
    const int e   = blockIdx.z;
    const int cnt = d_cnt[e];
    const int m0  = blockIdx.y * BM;
    if (m0 >= cnt) return;
    const int n0  = blockIdx.x * BN;

    __shared__ float As[KT][BM];
    __shared__ float Bs[KT][BN];

    const int tid = threadIdx.x;
    const int tx  = tid & 15;
    const int ty  = tid >> 4;

    const float* w2e  = w2 + (size_t)e * HDIM * IDIM + (size_t)n0 * IDIM;
    const float* acte = d_act + (size_t)e * CAP * IDIM;

    unsigned long long acc[4][4];
    #pragma unroll
    for (int i = 0; i < 4; i++)
        #pragma unroll
        for (int j = 0; j < 4; j++) acc[i][j] = 0ull;

    for (int k0 = 0; k0 < IDIM; k0 += KT) {
        #pragma unroll
        for (int i = 0; i < 2; i++) {
            int idx = tid + i * 256;
            int row = idx >> 2, q = idx & 3;   // m0+row < CAP always; stale rows are finite & discarded
            float4 v = *reinterpret_cast<const float4*>(acte + (size_t)(m0 + row) * IDIM + k0 + q * 4);
            As[q * 4 + 0][row] = v.x; As[q * 4 + 1][row] = v.y;
            As[q * 4 + 2][row] = v.z; As[q * 4 + 3][row] = v.w;
        }
        {
            int row = tid >> 2, q = tid & 3;
            float4 v = *reinterpret_cast<const float4*>(w2e + (size_t)row * IDIM + k0 + q * 4);
            Bs[q * 4 + 0][row] = v.x; Bs[q * 4 + 1][row] = v.y;
            Bs[q * 4 + 2][row] = v.z; Bs[q * 4 + 3][row] = v.w;
        }
        __syncthreads();

        #pragma unroll
        for (int kk = 0; kk < KT; kk++) {
            ulonglong2 a01 = *reinterpret_cast<const ulonglong2*>(&As[kk][ty * 8]);
            ulonglong2 a23 = *reinterpret_cast<const ulonglong2*>(&As[kk][ty * 8 + 4]);
            unsigned long long ap[4] = { a01.x, a01.y, a23.x, a23.y };
            float4 b4 = *reinterpret_cast<const float4*>(&Bs[kk][tx * 4]);
            unsigned long long bb[4];
            PACK2(bb[0], b4.x); PACK2(bb[1], b4.y); PACK2(bb[2], b4.z); PACK2(bb[3], b4.w);
            #pragma unroll
            for (int mp = 0; mp < 4; mp++)
                #pragma unroll
                for (int n = 0; n < 4; n++)
                    FFMA2(acc[mp][n], ap[mp], bb[n]);
        }
        __syncthreads();
    }

    // ---- epilogue: out[tok, n] += weight * acc ----
    #pragma unroll
    for (int mp = 0; mp < 4; mp++) {
        int r0 = m0 + ty * 8 + 2 * mp;
        int r1 = r0 + 1;
        float vlo[4], vhi[4];
        #pragma unroll
        for (int n = 0; n < 4; n++) UNPACK2(vlo[n], vhi[n], acc[mp][n]);
        if (r0 < cnt) {
            float w = d_wt[e * CAP + r0];
            int tok  = d_tok[e * CAP + r0];
            float* o = out + (size_t)tok * HDIM + n0 + tx * 4;
            #pragma unroll
            for (int n = 0; n < 4; n++) atomicAdd(o + n, w * vlo[n]);
        }
        if (r1 < cnt) {
            float w = d_wt[e * CAP + r1];
            int tok  = d_tok[e * CAP + r1];
            float* o = out + (size_t)tok * HDIM + n0 + tx * 4;
            #pragma unroll
            for (int n = 0; n < 4; n++) atomicAdd(o + n, w * vhi[n]);
        }
    }
}

// ============================================================
// launch
// ============================================================
extern "C" void kernel_launch(void* const* d_in, const int* in_sizes, int n_in,
                              void* d_out, int out_size) {
    const float* x  = (const float*)d_in[0];   // hidden_states [1,1024,2048]
    const float* gw = (const float*)d_in[1];   // gate_w [16,2048]
    const float* w1 = (const float*)d_in[2];   // w1 [16,1536,2048]
    const float* w2 = (const float*)d_in[3];   // w2 [16,2048,768]
    float* out    = (float*)d_out;                         // [1024,2048]
    float* logits = (float*)d_out + (size_t)T_TOK * HDIM;  // [1024,16]

    (void)in_sizes; (void)n_in; (void)out_size;

    zero_kernel  <<< (T_TOK * HDIM / 4) / 256, 256 >>> (out);
    router_kernel<<< T_TOK / 8, 256 >>> (x, gw, logits);
    gemm1_kernel <<< dim3(IDIM / BN, T_TOK / BM, NEXP), 256 >>> (x, w1);
    gemm2_kernel <<< dim3(HDIM / BN, T_TOK / BM, NEXP), 256 >>> (w2, out);
}

// round 6
// speedup vs baseline: 1.0487x; 1.0487x over previous
#include <cuda_runtime.h>
#include <math.h>

#define T_TOK 1024
#define HDIM  2048
#define NEXP  16
#define IDIM  768
#define CAP   1024   // worst-case tokens per expert

// -------- device scratch (no allocs allowed) --------
__device__ int   d_cnt[NEXP];
__device__ int   d_tok[NEXP * CAP];
__device__ float d_wt [NEXP * CAP];
__device__ float d_act[(size_t)NEXP * CAP * IDIM];   // ~50 MB, zero-init; rows >= cnt stay zero

// -------- packed f32x2 helpers (sm_103a) --------
#define FFMA2(acc, a, b) \
    asm("fma.rn.f32x2 %0, %1, %2, %0;" : "+l"(acc) : "l"(a), "l"(b))

#define PACK2(out, f) do { \
    unsigned int _u = __float_as_uint(f); \
    asm("mov.b64 %0, {%1, %1};" : "=l"(out) : "r"(_u)); \
} while (0)

#define UNPACK2(lo, hi, in) do { \
    unsigned int _l, _h; \
    asm("mov.b64 {%0, %1}, %2;" : "=r"(_l), "=r"(_h) : "l"(in)); \
    lo = __uint_as_float(_l); hi = __uint_as_float(_h); \
} while (0)

// ============================================================
// Kernel 0: zero output accumulator region + expert counters
// ============================================================
__global__ void zero_kernel(float* __restrict__ out) {
    int i = blockIdx.x * blockDim.x + threadIdx.x;    // T*H/4 float4
    float4 z = make_float4(0.f, 0.f, 0.f, 0.f);
    reinterpret_cast<float4*>(out)[i] = z;
    if (blockIdx.x == 0 && threadIdx.x < NEXP) d_cnt[threadIdx.x] = 0;
}

// ============================================================
// Kernel 1: router — logits, top-2, normalized weights, token lists
// one warp per token
// ============================================================
__global__ __launch_bounds__(256) void router_kernel(
    const float* __restrict__ x,        // [T, H]
    const float* __restrict__ gw,       // [E, H]
    float* __restrict__ logits_out)     // [T, E]
{
    int warp = threadIdx.x >> 5;
    int lane = threadIdx.x & 31;
    int t = blockIdx.x * 8 + warp;
    __shared__ float lg[8][NEXP];

    const float* xr = x + (size_t)t * HDIM;
    #pragma unroll 1
    for (int e = 0; e < NEXP; e++) {
        const float* g = gw + (size_t)e * HDIM;
        float s = 0.f;
        for (int k = lane * 4; k < HDIM; k += 128) {
            float4 xv = *reinterpret_cast<const float4*>(xr + k);
            float4 gv = *reinterpret_cast<const float4*>(g + k);
            s += xv.x * gv.x + xv.y * gv.y + xv.z * gv.z + xv.w * gv.w;
        }
        #pragma unroll
        for (int o = 16; o; o >>= 1) s += __shfl_xor_sync(0xffffffffu, s, o);
        if (lane == 0) lg[warp][e] = s;
    }
    __syncwarp();

    if (lane < NEXP) logits_out[t * NEXP + lane] = lg[warp][lane];

    if (lane == 0) {
        int i0 = 0; float v0 = lg[warp][0];
        #pragma unroll
        for (int e = 1; e < NEXP; e++) { float v = lg[warp][e]; if (v > v0) { v0 = v; i0 = e; } }
        int i1 = -1; float v1 = -3.4e38f;
        #pragma unroll
        for (int e = 0; e < NEXP; e++) { if (e == i0) continue; float v = lg[warp][e]; if (v > v1) { v1 = v; i1 = e; } }
        float w0 = 1.f / (1.f + expf(v1 - v0));   // softmax normalizer cancels
        float w1 = 1.f - w0;
        int p0 = atomicAdd(&d_cnt[i0], 1);
        d_tok[i0 * CAP + p0] = t;  d_wt[i0 * CAP + p0] = w0;
        int p1 = atomicAdd(&d_cnt[i1], 1);
        d_tok[i1 * CAP + p1] = t;  d_wt[i1 * CAP + p1] = w1;
    }
}

// ============================================================
// Kernel 2: grouped GEMM1 + fused SiLU·up
//   per expert e: act[cnt, 768] = silu(X w1g^T) * (X w1u^T)
//   128 threads, BM=64 tokens, BN=64 act-cols (gate + up together),
//   KT=16, double-buffered smem, per-thread 8m x (4g + 4u) f32x2 tiles
// ============================================================
#define G1_BM 64
#define G1_BN 64
#define G1_KT 16
#define G1_ITERS (HDIM / G1_KT)   // 128

__global__ __launch_bounds__(128) void gemm1_kernel(
    const float* __restrict__ x,     // [T, H]
    const float* __restrict__ w1)    // [E, 2I, H]
{
    const int e   = blockIdx.z;
    const int cnt = d_cnt[e];
    const int m0  = blockIdx.y * G1_BM;
    if (m0 >= cnt) return;
    const int n0  = blockIdx.x * G1_BN;

    __shared__ float As[2][G1_KT][G1_BM];
    __shared__ float Gs[2][G1_KT][G1_BN];
    __shared__ float Us[2][G1_KT][G1_BN];

    const int tid  = threadIdx.x;
    const int tx   = tid & 15;      // n quad
    const int ty   = tid >> 4;      // m octet (0..7)
    const int lrow = tid & 63;
    const int lq   = tid >> 6;      // 0..1

    int gr  = m0 + lrow;
    int tok = (gr < cnt) ? d_tok[e * CAP + gr] : 0;
    const float* arow = x + (size_t)tok * HDIM;
    const float* grow = w1 + (size_t)e * (2 * IDIM) * HDIM + (size_t)(n0 + lrow) * HDIM;
    const float* urow = grow + (size_t)IDIM * HDIM;

    float4 pa[2], pg[2], pu[2];
    #pragma unroll
    for (int i = 0; i < 2; i++) {
        int q = lq + 2 * i;
        pa[i] = *reinterpret_cast<const float4*>(arow + q * 4);
        pg[i] = *reinterpret_cast<const float4*>(grow + q * 4);
        pu[i] = *reinterpret_cast<const float4*>(urow + q * 4);
    }
    #pragma unroll
    for (int i = 0; i < 2; i++) {
        int q = lq + 2 * i;
        As[0][q*4+0][lrow] = pa[i].x; As[0][q*4+1][lrow] = pa[i].y;
        As[0][q*4+2][lrow] = pa[i].z; As[0][q*4+3][lrow] = pa[i].w;
        Gs[0][q*4+0][lrow] = pg[i].x; Gs[0][q*4+1][lrow] = pg[i].y;
        Gs[0][q*4+2][lrow] = pg[i].z; Gs[0][q*4+3][lrow] = pg[i].w;
        Us[0][q*4+0][lrow] = pu[i].x; Us[0][q*4+1][lrow] = pu[i].y;
        Us[0][q*4+2][lrow] = pu[i].z; Us[0][q*4+3][lrow] = pu[i].w;
    }
    __syncthreads();

    unsigned long long accG[8][2], accU[8][2];
    #pragma unroll
    for (int mi = 0; mi < 8; mi++) {
        accG[mi][0] = 0ull; accG[mi][1] = 0ull;
        accU[mi][0] = 0ull; accU[mi][1] = 0ull;
    }

    for (int it = 0; it < G1_ITERS; it++) {
        const int cur = it & 1;
        const bool has_next = (it + 1 < G1_ITERS);
        if (has_next) {
            int k0 = (it + 1) * G1_KT;
            #pragma unroll
            for (int i = 0; i < 2; i++) {
                int q = lq + 2 * i;
                pa[i] = *reinterpret_cast<const float4*>(arow + k0 + q * 4);
                pg[i] = *reinterpret_cast<const float4*>(grow + k0 + q * 4);
                pu[i] = *reinterpret_cast<const float4*>(urow + k0 + q * 4);
            }
        }
        #pragma unroll
        for (int kk = 0; kk < G1_KT; kk++) {
            float4 a0 = *reinterpret_cast<const float4*>(&As[cur][kk][ty * 8]);
            float4 a1 = *reinterpret_cast<const float4*>(&As[cur][kk][ty * 8 + 4]);
            unsigned long long ap[8];
            PACK2(ap[0], a0.x); PACK2(ap[1], a0.y); PACK2(ap[2], a0.z); PACK2(ap[3], a0.w);
            PACK2(ap[4], a1.x); PACK2(ap[5], a1.y); PACK2(ap[6], a1.z); PACK2(ap[7], a1.w);
            ulonglong2 g2 = *reinterpret_cast<const ulonglong2*>(&Gs[cur][kk][tx * 4]);
            ulonglong2 u2 = *reinterpret_cast<const ulonglong2*>(&Us[cur][kk][tx * 4]);
            #pragma unroll
            for (int mi = 0; mi < 8; mi++) {
                FFMA2(accG[mi][0], ap[mi], g2.x);
                FFMA2(accG[mi][1], ap[mi], g2.y);
                FFMA2(accU[mi][0], ap[mi], u2.x);
                FFMA2(accU[mi][1], ap[mi], u2.y);
            }
        }
        if (has_next) {
            const int nxt = cur ^ 1;
            #pragma unroll
            for (int i = 0; i < 2; i++) {
                int q = lq + 2 * i;
                As[nxt][q*4+0][lrow] = pa[i].x; As[nxt][q*4+1][lrow] = pa[i].y;
                As[nxt][q*4+2][lrow] = pa[i].z; As[nxt][q*4+3][lrow] = pa[i].w;
                Gs[nxt][q*4+0][lrow] = pg[i].x; Gs[nxt][q*4+1][lrow] = pg[i].y;
                Gs[nxt][q*4+2][lrow] = pg[i].z; Gs[nxt][q*4+3][lrow] = pg[i].w;
                Us[nxt][q*4+0][lrow] = pu[i].x; Us[nxt][q*4+1][lrow] = pu[i].y;
                Us[nxt][q*4+2][lrow] = pu[i].z; Us[nxt][q*4+3][lrow] = pu[i].w;
            }
            __syncthreads();
        }
    }

    // epilogue: act = silu(g) * u, store float4 per row
    #pragma unroll
    for (int mi = 0; mi < 8; mi++) {
        int r = m0 + ty * 8 + mi;
        if (r < cnt) {
            float g0, g1, g2v, g3, u0, u1, u2v, u3;
            UNPACK2(g0, g1, accG[mi][0]); UNPACK2(g2v, g3, accG[mi][1]);
            UNPACK2(u0, u1, accU[mi][0]); UNPACK2(u2v, u3, accU[mi][1]);
            float4 o;
            o.x = g0 / (1.f + __expf(-g0)) * u0;
            o.y = g1 / (1.f + __expf(-g1)) * u1;
            o.z = g2v / (1.f + __expf(-g2v)) * u2v;
            o.w = g3 / (1.f + __expf(-g3)) * u3;
            *reinterpret_cast<float4*>(d_act + ((size_t)e * CAP + r) * IDIM + n0 + tx * 4) = o;
        }
    }
}

// ============================================================
// Kernel 3: grouped GEMM2 + weighted atomic scatter-add
//   per expert e: out[tok] += w * (act_e @ w2_e^T)
//   128 threads, BM=64, BN=128, KT=16, double-buffered,
//   per-thread 8m x 8n (two n-quads: tx*4 and 64+tx*4)
// ============================================================
#define G2_BM 64
#define G2_BN 128
#define G2_KT 16
#define G2_ITERS (IDIM / G2_KT)   // 48

__global__ __launch_bounds__(128) void gemm2_kernel(
    const float* __restrict__ w2,    // [E, H, I]
    float* __restrict__ out)         // [T, H]
{
    const int e   = blockIdx.z;
    const int cnt = d_cnt[e];
    const int m0  = blockIdx.y * G2_BM;
    if (m0 >= cnt) return;
    const int n0  = blockIdx.x * G2_BN;

    __shared__ float As[2][G2_KT][G2_BM];     // 8 KB
    __shared__ float Bs[2][G2_KT][G2_BN];     // 16 KB

    const int tid  = threadIdx.x;
    const int tx   = tid & 15;
    const int ty   = tid >> 4;
    const int lrow = tid & 63;
    const int lq   = tid >> 6;

    // act rows >= cnt are zero (never written) -> safe to read
    const float* arow = d_act + ((size_t)e * CAP + m0 + lrow) * IDIM;
    const float* brow = w2 + (size_t)e * HDIM * IDIM + (size_t)(n0 + tid) * IDIM;

    float4 pa[2], pb[4];
    #pragma unroll
    for (int i = 0; i < 2; i++) {
        int q = lq + 2 * i;
        pa[i] = *reinterpret_cast<const float4*>(arow + q * 4);
    }
    #pragma unroll
    for (int q = 0; q < 4; q++)
        pb[q] = *reinterpret_cast<const float4*>(brow + q * 4);

    #pragma unroll
    for (int i = 0; i < 2; i++) {
        int q = lq + 2 * i;
        As[0][q*4+0][lrow] = pa[i].x; As[0][q*4+1][lrow] = pa[i].y;
        As[0][q*4+2][lrow] = pa[i].z; As[0][q*4+3][lrow] = pa[i].w;
    }
    #pragma unroll
    for (int q = 0; q < 4; q++) {
        Bs[0][q*4+0][tid] = pb[q].x; Bs[0][q*4+1][tid] = pb[q].y;
        Bs[0][q*4+2][tid] = pb[q].z; Bs[0][q*4+3][tid] = pb[q].w;
    }
    __syncthreads();

    unsigned long long acc[8][4];
    #pragma unroll
    for (int mi = 0; mi < 8; mi++)
        #pragma unroll
        for (int j = 0; j < 4; j++) acc[mi][j] = 0ull;

    for (int it = 0; it < G2_ITERS; it++) {
        const int cur = it & 1;
        const bool has_next = (it + 1 < G2_ITERS);
        if (has_next) {
            int k0 = (it + 1) * G2_KT;
            #pragma unroll
            for (int i = 0; i < 2; i++) {
                int q = lq + 2 * i;
                pa[i] = *reinterpret_cast<const float4*>(arow + k0 + q * 4);
            }
            #pragma unroll
            for (int q = 0; q < 4; q++)
                pb[q] = *reinterpret_cast<const float4*>(brow + k0 + q * 4);
        }
        #pragma unroll
        for (int kk = 0; kk < G2_KT; kk++) {
            float4 a0 = *reinterpret_cast<const float4*>(&As[cur][kk][ty * 8]);
            float4 a1 = *reinterpret_cast<const float4*>(&As[cur][kk][ty * 8 + 4]);
            unsigned long long ap[8];
            PACK2(ap[0], a0.x); PACK2(ap[1], a0.y); PACK2(ap[2], a0.z); PACK2(ap[3], a0.w);
            PACK2(ap[4], a1.x); PACK2(ap[5], a1.y); PACK2(ap[6], a1.z); PACK2(ap[7], a1.w);
            ulonglong2 b0 = *reinterpret_cast<const ulonglong2*>(&Bs[cur][kk][tx * 4]);
            ulonglong2 b1 = *reinterpret_cast<const ulonglong2*>(&Bs[cur][kk][64 + tx * 4]);
            #pragma unroll
            for (int mi = 0; mi < 8; mi++) {
                FFMA2(acc[mi][0], ap[mi], b0.x);
                FFMA2(acc[mi][1], ap[mi], b0.y);
                FFMA2(acc[mi][2], ap[mi], b1.x);
                FFMA2(acc[mi][3], ap[mi], b1.y);
            }
        }
        if (has_next) {
            const int nxt = cur ^ 1;
            #pragma unroll
            for (int i = 0; i < 2; i++) {
                int q = lq + 2 * i;
                As[nxt][q*4+0][lrow] = pa[i].x; As[nxt][q*4+1][lrow] = pa[i].y;
                As[nxt][q*4+2][lrow] = pa[i].z; As[nxt][q*4+3][lrow] = pa[i].w;
            }
            #pragma unroll
            for (int q = 0; q < 4; q++) {
                Bs[nxt][q*4+0][tid] = pb[q].x; Bs[nxt][q*4+1][tid] = pb[q].y;
                Bs[nxt][q*4+2][tid] = pb[q].z; Bs[nxt][q*4+3][tid] = pb[q].w;
            }
            __syncthreads();
        }
    }

    // epilogue: out[tok, n] += weight * acc
    #pragma unroll
    for (int mi = 0; mi < 8; mi++) {
        int r = m0 + ty * 8 + mi;
        if (r < cnt) {
            float w   = d_wt[e * CAP + r];
            int   tok = d_tok[e * CAP + r];
            float* o  = out + (size_t)tok * HDIM + n0;
            float v0, v1, v2, v3, v4, v5, v6, v7;
            UNPACK2(v0, v1, acc[mi][0]); UNPACK2(v2, v3, acc[mi][1]);
            UNPACK2(v4, v5, acc[mi][2]); UNPACK2(v6, v7, acc[mi][3]);
            atomicAdd(o + tx * 4 + 0, w * v0);
            atomicAdd(o + tx * 4 + 1, w * v1);
            atomicAdd(o + tx * 4 + 2, w * v2);
            atomicAdd(o + tx * 4 + 3, w * v3);
            atomicAdd(o + 64 + tx * 4 + 0, w * v4);
            atomicAdd(o + 64 + tx * 4 + 1, w * v5);
            atomicAdd(o + 64 + tx * 4 + 2, w * v6);
            atomicAdd(o + 64 + tx * 4 + 3, w * v7);
        }
    }
}

// ============================================================
// launch
// ============================================================
extern "C" void kernel_launch(void* const* d_in, const int* in_sizes, int n_in,
                              void* d_out, int out_size) {
    const float* x  = (const float*)d_in[0];   // hidden_states [1,1024,2048]
    const float* gw = (const float*)d_in[1];   // gate_w [16,2048]
    const float* w1 = (const float*)d_in[2];   // w1 [16,1536,2048]
    const float* w2 = (const float*)d_in[3];   // w2 [16,2048,768]
    float* out    = (float*)d_out;                         // [1024,2048]
    float* logits = (float*)d_out + (size_t)T_TOK * HDIM;  // [1024,16]

    (void)in_sizes; (void)n_in; (void)out_size;

    zero_kernel  <<< (T_TOK * HDIM / 4) / 256, 256 >>> (out);
    router_kernel<<< T_TOK / 8, 256 >>> (x, gw, logits);
    gemm1_kernel <<< dim3(IDIM / G1_BN, CAP / G1_BM, NEXP), 128 >>> (x, w1);
    gemm2_kernel <<< dim3(HDIM / G2_BN, CAP / G2_BM, NEXP), 128 >>> (w2, out);
}